// round 2
// baseline (speedup 1.0000x reference)
#include <cuda_runtime.h>
#include <cstdint>

// Problem constants (fixed by the reference)
#define BSZ   4
#define NTOK  4096
#define DDIM  1024
#define EEXP  8
#define TCNT  (BSZ*NTOK)     // 16384 tokens
#define KSEL  2
#define CAP   TCNT           // worst-case rows per expert
#define DFF   (2*DDIM)       // 2048

#define TM 128
#define TN 128
#define TK 8

// Max padded rows across all experts: 32768 assignments + 8*(TM-1) padding,
// rounded up to tile multiples -> 264 tiles of 128 rows.
#define MAXTILES 264
#define MAXROWS  (MAXTILES * TM)   // 33792

// ---------------- device scratch (static; compact, ~400 MB total) ----------
__device__ int   g_cnt[EEXP];
__device__ int   g_off[EEXP + 1];            // padded row offsets per expert
__device__ int   g_tok[EEXP * CAP];          // expert-slab token lists
__device__ float g_gate[EEXP * CAP];         // expert-slab gate values
__device__ int   g_pos[2 * TCNT];            // per token: 2 slab coords e*CAP+slot
__device__ float g_H[(size_t)MAXROWS * DFF]; // relu(x@W1+b1), compact rows (264 MB)
__device__ float g_Y[(size_t)MAXROWS * DDIM];// h@W2+b2 per assignment     (132 MB)

// ---------------- kernel 0: reset counters ----------------------------------
__global__ void init_kernel() {
    if (threadIdx.x < EEXP) g_cnt[threadIdx.x] = 0;
}

// ---------------- kernel 1: gating ------------------------------------------
// 8 warps/block, one token per warp. Wg transposed into smem [E][D].
__global__ void gating_kernel(const float* __restrict__ x,
                              const float* __restrict__ Wg,
                              const float* __restrict__ bg) {
    __shared__ float sWgT[EEXP][DDIM];   // 32 KB
    int tid = threadIdx.x;
    for (int i = tid; i < EEXP * DDIM; i += blockDim.x) {
        int k = i >> 3;          // Wg is [D, E] row-major: i = k*8 + e
        int e = i & 7;
        sWgT[e][k] = Wg[i];
    }
    __syncthreads();

    int warp = tid >> 5;
    int lane = tid & 31;
    int t = blockIdx.x * 8 + warp;

    float acc[EEXP];
#pragma unroll
    for (int e = 0; e < EEXP; e++) acc[e] = 0.f;

    const float* xr = x + (size_t)t * DDIM;
    for (int k = lane; k < DDIM; k += 32) {
        float xv = xr[k];
#pragma unroll
        for (int e = 0; e < EEXP; e++) acc[e] += xv * sWgT[e][k];
    }
#pragma unroll
    for (int e = 0; e < EEXP; e++) {
#pragma unroll
        for (int off = 16; off > 0; off >>= 1)
            acc[e] += __shfl_xor_sync(0xFFFFFFFFu, acc[e], off);
    }

    if (lane == 0) {
        float l[EEXP];
#pragma unroll
        for (int e = 0; e < EEXP; e++) l[e] = acc[e] + bg[e];
        // top-2, lowest-index tie-break (matches lax.top_k)
        int i1 = 0;
#pragma unroll
        for (int e = 1; e < EEXP; e++) if (l[e] > l[i1]) i1 = e;
        int i2 = (i1 == 0) ? 1 : 0;
#pragma unroll
        for (int e = 0; e < EEXP; e++) if (e != i1 && l[e] > l[i2]) i2 = e;
        float p2 = expf(l[i2] - l[i1]);
        float s  = 1.f + p2;
        int s1 = atomicAdd(&g_cnt[i1], 1);
        g_tok[i1 * CAP + s1]  = t;
        g_gate[i1 * CAP + s1] = 1.f / s;
        g_pos[2 * t + 0] = i1 * CAP + s1;
        int s2 = atomicAdd(&g_cnt[i2], 1);
        g_tok[i2 * CAP + s2]  = t;
        g_gate[i2 * CAP + s2] = p2 / s;
        g_pos[2 * t + 1] = i2 * CAP + s2;
    }
}

// ---------------- kernel 2: padded prefix offsets ---------------------------
__global__ void offsets_kernel() {
    if (threadIdx.x == 0) {
        int acc = 0;
#pragma unroll
        for (int e = 0; e < EEXP; e++) {
            g_off[e] = acc;
            acc += ((g_cnt[e] + TM - 1) / TM) * TM;
        }
        g_off[EEXP] = acc;
    }
}

// Map a global padded tile index -> (expert, local m0). Returns -1 to skip.
__device__ __forceinline__ int tile_to_expert(int row0, int& m0) {
    if (row0 >= g_off[EEXP]) return -1;
    int e = 0;
#pragma unroll
    for (int k = 1; k < EEXP; k++) if (row0 >= g_off[k]) e = k;
    m0 = row0 - g_off[e];
    if (m0 >= g_cnt[e]) return -1;   // padding tile
    return e;
}

// ---------------- kernel 3: ffn1  H = relu(gather(x) @ W1[e] + b1[e]) -------
__global__ void __launch_bounds__(256, 2)
ffn1_kernel(const float* __restrict__ x,
            const float* __restrict__ W1,
            const float* __restrict__ b1) {
    int row0 = blockIdx.y * TM;
    int m0;
    int e = tile_to_expert(row0, m0);
    if (e < 0) return;
    int n_rows = g_cnt[e];
    int n0 = blockIdx.x * TN;

    const float* W = W1 + (size_t)e * DDIM * DFF;   // [1024, 2048] row-major
    const int*   toks = g_tok + e * CAP + m0;
    float* Hp = g_H + (size_t)row0 * DFF;

    __shared__ float As[TK][TM];
    __shared__ float Bs[TK][TN];

    int tid = threadIdx.x;
    int a_m = tid >> 1;
    int a_k = (tid & 1) * 4;
    int a_tok = (m0 + a_m < n_rows) ? toks[a_m] : toks[0];
    const float* a_ptr = x + (size_t)a_tok * DDIM + a_k;
    int b_k = tid >> 5;
    int b_n = (tid & 31) * 4;
    const float* b_ptr = W + (size_t)b_k * DFF + n0 + b_n;

    int tm = (tid >> 4) * 8;
    int tn = (tid & 15) * 8;

    float acc[8][8];
#pragma unroll
    for (int i = 0; i < 8; i++)
#pragma unroll
        for (int j = 0; j < 8; j++) acc[i][j] = 0.f;

    for (int k0 = 0; k0 < DDIM; k0 += TK) {
        float4 av = *(const float4*)(a_ptr + k0);
        float4 bv = *(const float4*)(b_ptr + (size_t)k0 * DFF);
        __syncthreads();
        As[a_k + 0][a_m] = av.x;
        As[a_k + 1][a_m] = av.y;
        As[a_k + 2][a_m] = av.z;
        As[a_k + 3][a_m] = av.w;
        *(float4*)&Bs[b_k][b_n] = bv;
        __syncthreads();
#pragma unroll
        for (int kk = 0; kk < TK; kk++) {
            float4 a0 = *(const float4*)&As[kk][tm];
            float4 a1 = *(const float4*)&As[kk][tm + 4];
            float4 bq0 = *(const float4*)&Bs[kk][tn];
            float4 bq1 = *(const float4*)&Bs[kk][tn + 4];
            float ra[8] = {a0.x, a0.y, a0.z, a0.w, a1.x, a1.y, a1.z, a1.w};
            float rb[8] = {bq0.x, bq0.y, bq0.z, bq0.w, bq1.x, bq1.y, bq1.z, bq1.w};
#pragma unroll
            for (int i = 0; i < 8; i++)
#pragma unroll
                for (int j = 0; j < 8; j++) acc[i][j] += ra[i] * rb[j];
        }
    }

    const float* b1e = b1 + (size_t)e * DFF + n0 + tn;
#pragma unroll
    for (int i = 0; i < 8; i++) {
        float* hp = Hp + (size_t)(tm + i) * DFF + n0 + tn;
#pragma unroll
        for (int j = 0; j < 8; j += 4) {
            float4 v;
            v.x = fmaxf(acc[i][j + 0] + b1e[j + 0], 0.f);
            v.y = fmaxf(acc[i][j + 1] + b1e[j + 1], 0.f);
            v.z = fmaxf(acc[i][j + 2] + b1e[j + 2], 0.f);
            v.w = fmaxf(acc[i][j + 3] + b1e[j + 3], 0.f);
            *(float4*)(hp + j) = v;
        }
    }
}

// ---------------- kernel 4: ffn2  Y = H @ W2[e] + b2[e] (disjoint rows) -----
__global__ void __launch_bounds__(256, 2)
ffn2_kernel(const float* __restrict__ W2,
            const float* __restrict__ b2) {
    int row0 = blockIdx.y * TM;
    int m0;
    int e = tile_to_expert(row0, m0);
    if (e < 0) return;
    int n0 = blockIdx.x * TN;

    const float* W = W2 + (size_t)e * DFF * DDIM;   // [2048, 1024] row-major
    const float* Ap = g_H + (size_t)row0 * DFF;
    float* Yp = g_Y + (size_t)row0 * DDIM;

    __shared__ float As[TK][TM];
    __shared__ float Bs[TK][TN];

    int tid = threadIdx.x;
    int a_m = tid >> 1;
    int a_k = (tid & 1) * 4;
    const float* a_ptr = Ap + (size_t)a_m * DFF + a_k;
    int b_k = tid >> 5;
    int b_n = (tid & 31) * 4;
    const float* b_ptr = W + (size_t)b_k * DDIM + n0 + b_n;

    int tm = (tid >> 4) * 8;
    int tn = (tid & 15) * 8;

    float acc[8][8];
#pragma unroll
    for (int i = 0; i < 8; i++)
#pragma unroll
        for (int j = 0; j < 8; j++) acc[i][j] = 0.f;

    for (int k0 = 0; k0 < DFF; k0 += TK) {
        float4 av = *(const float4*)(a_ptr + k0);
        float4 bv = *(const float4*)(b_ptr + (size_t)k0 * DDIM);
        __syncthreads();
        As[a_k + 0][a_m] = av.x;
        As[a_k + 1][a_m] = av.y;
        As[a_k + 2][a_m] = av.z;
        As[a_k + 3][a_m] = av.w;
        *(float4*)&Bs[b_k][b_n] = bv;
        __syncthreads();
#pragma unroll
        for (int kk = 0; kk < TK; kk++) {
            float4 a0 = *(const float4*)&As[kk][tm];
            float4 a1 = *(const float4*)&As[kk][tm + 4];
            float4 bq0 = *(const float4*)&Bs[kk][tn];
            float4 bq1 = *(const float4*)&Bs[kk][tn + 4];
            float ra[8] = {a0.x, a0.y, a0.z, a0.w, a1.x, a1.y, a1.z, a1.w};
            float rb[8] = {bq0.x, bq0.y, bq0.z, bq0.w, bq1.x, bq1.y, bq1.z, bq1.w};
#pragma unroll
            for (int i = 0; i < 8; i++)
#pragma unroll
                for (int j = 0; j < 8; j++) acc[i][j] += ra[i] * rb[j];
        }
    }

    const float* b2e = b2 + (size_t)e * DDIM + n0 + tn;
#pragma unroll
    for (int i = 0; i < 8; i++) {
        float* yp = Yp + (size_t)(tm + i) * DDIM + n0 + tn;
#pragma unroll
        for (int j = 0; j < 8; j += 4) {
            float4 v;
            v.x = acc[i][j + 0] + b2e[j + 0];
            v.y = acc[i][j + 1] + b2e[j + 1];
            v.z = acc[i][j + 2] + b2e[j + 2];
            v.w = acc[i][j + 3] + b2e[j + 3];
            *(float4*)(yp + j) = v;
        }
    }
}

// ---------------- kernel 5: combine  out[t] = g1*Y[r1] + g2*Y[r2] -----------
__global__ void combine_kernel(float* __restrict__ out) {
    int t = blockIdx.x;
    int c = threadIdx.x * 4;           // 256 threads x 4 floats = 1024
    int p1 = g_pos[2 * t + 0];
    int p2 = g_pos[2 * t + 1];
    int e1 = p1 / CAP, e2 = p2 / CAP;
    size_t r1 = (size_t)(g_off[e1] + (p1 - e1 * CAP)) * DDIM;
    size_t r2 = (size_t)(g_off[e2] + (p2 - e2 * CAP)) * DDIM;
    float gv1 = g_gate[p1];
    float gv2 = g_gate[p2];
    float4 y1 = *(const float4*)(g_Y + r1 + c);
    float4 y2 = *(const float4*)(g_Y + r2 + c);
    float4 o;
    o.x = gv1 * y1.x + gv2 * y2.x;
    o.y = gv1 * y1.y + gv2 * y2.y;
    o.z = gv1 * y1.z + gv2 * y2.z;
    o.w = gv1 * y1.w + gv2 * y2.w;
    *(float4*)(out + (size_t)t * DDIM + c) = o;
}

// ---------------- launch ----------------------------------------------------
extern "C" void kernel_launch(void* const* d_in, const int* in_sizes, int n_in,
                              void* d_out, int out_size) {
    const float* x  = (const float*)d_in[0];
    const float* Wg = (const float*)d_in[1];
    const float* bg = (const float*)d_in[2];
    const float* W1 = (const float*)d_in[3];
    const float* b1 = (const float*)d_in[4];
    const float* W2 = (const float*)d_in[5];
    const float* b2 = (const float*)d_in[6];
    float* out = (float*)d_out;

    init_kernel<<<1, 32>>>();
    gating_kernel<<<TCNT / 8, 256>>>(x, Wg, bg);
    offsets_kernel<<<1, 32>>>();

    dim3 g1(DFF / TN, MAXTILES);       // (16, 264)
    ffn1_kernel<<<g1, 256>>>(x, W1, b1);

    dim3 g2(DDIM / TN, MAXTILES);      // (8, 264)
    ffn2_kernel<<<g2, 256>>>(W2, b2);

    combine_kernel<<<TCNT, 256>>>(out);
}

// round 4
// speedup vs baseline: 3.1272x; 3.1272x over previous
#include <cuda_runtime.h>
#include <cstdint>

// Problem constants
#define BSZ   4
#define NTOK  4096
#define DDIM  1024
#define EEXP  8
#define TCNT  (BSZ*NTOK)     // 16384 tokens
#define CAP   TCNT
#define DFF   (2*DDIM)       // 2048

#define TM 128
#define TN 128
#define KC 16                // K floats per stage
#define SROW 20              // padded floats per smem row (bank-conflict-free)
#define STAGE_BYTES (TM*SROW*4*2)            // A(10240) + B(10240) = 20480
#define SMEM_BYTES  (1024 + 1024 + 2*STAGE_BYTES)  // 43008 < 48KB

#define MAXTILES 264
#define MAXROWS  (MAXTILES * TM)             // 33792

// ---------------- device scratch -------------------------------------------
__device__ int   g_cnt[EEXP];
__device__ int   g_off[EEXP + 1];
__device__ int   g_tok[EEXP * CAP];
__device__ float g_gate[EEXP * CAP];
__device__ int   g_pos[2 * TCNT];
__device__ float g_X[(size_t)TCNT * DDIM];          // tf32-rounded x (64 MB)
__device__ float g_H[(size_t)MAXROWS * DFF];        // tf32-rounded relu(xW1+b1)
__device__ float g_Y[(size_t)MAXROWS * DDIM];       // f32 hW2+b2
__device__ float g_W1T[(size_t)EEXP * DFF * DDIM];  // [E][N=2048][K=1024] rounded
__device__ float g_W2T[(size_t)EEXP * DDIM * DFF];  // [E][N=1024][K=2048] rounded

// ---------------- helpers ---------------------------------------------------
__device__ __forceinline__ uint32_t smem_u32(const void* p) {
    uint32_t a;
    asm("{ .reg .u64 t; cvta.to.shared.u64 t, %1; cvt.u32.u64 %0, t; }" : "=r"(a) : "l"(p));
    return a;
}
__device__ __forceinline__ float tf32r(float f) {
    uint32_t u;
    asm("cvt.rna.tf32.f32 %0, %1;" : "=r"(u) : "f"(f));
    return __uint_as_float(u);
}
#define CP16(dst, src) \
    asm volatile("cp.async.cg.shared.global [%0], [%1], 16;" :: "r"(dst), "l"(src))
#define CP_COMMIT() asm volatile("cp.async.commit_group;" ::: "memory")
#define CP_WAIT1()  asm volatile("cp.async.wait_group 1;" ::: "memory")
#define CP_WAIT0()  asm volatile("cp.async.wait_group 0;" ::: "memory")

#define MMA8(c, a, b0, b1) \
    asm volatile("mma.sync.aligned.m16n8k8.row.col.f32.tf32.tf32.f32 " \
        "{%0,%1,%2,%3}, {%4,%5,%6,%7}, {%8,%9}, {%0,%1,%2,%3};" \
        : "+f"((c)[0]), "+f"((c)[1]), "+f"((c)[2]), "+f"((c)[3]) \
        : "r"((a)[0]), "r"((a)[1]), "r"((a)[2]), "r"((a)[3]), "r"(b0), "r"(b1))

// ---------------- kernel 0: reset counters ----------------------------------
__global__ void init_kernel() {
    if (threadIdx.x < EEXP) g_cnt[threadIdx.x] = 0;
}

// ---------------- kernel 1: gating (exact fp32) ------------------------------
__global__ void gating_kernel(const float* __restrict__ x,
                              const float* __restrict__ Wg,
                              const float* __restrict__ bg) {
    __shared__ float sWgT[EEXP][DDIM];
    int tid = threadIdx.x;
    for (int i = tid; i < EEXP * DDIM; i += blockDim.x) {
        int k = i >> 3;
        int e = i & 7;
        sWgT[e][k] = Wg[i];
    }
    __syncthreads();

    int warp = tid >> 5;
    int lane = tid & 31;
    int t = blockIdx.x * 8 + warp;

    float acc[EEXP];
#pragma unroll
    for (int e = 0; e < EEXP; e++) acc[e] = 0.f;
    const float* xr = x + (size_t)t * DDIM;
    for (int k = lane; k < DDIM; k += 32) {
        float xv = xr[k];
#pragma unroll
        for (int e = 0; e < EEXP; e++) acc[e] += xv * sWgT[e][k];
    }
#pragma unroll
    for (int e = 0; e < EEXP; e++) {
#pragma unroll
        for (int off = 16; off > 0; off >>= 1)
            acc[e] += __shfl_xor_sync(0xFFFFFFFFu, acc[e], off);
    }
    if (lane == 0) {
        float l[EEXP];
#pragma unroll
        for (int e = 0; e < EEXP; e++) l[e] = acc[e] + bg[e];
        int i1 = 0;
#pragma unroll
        for (int e = 1; e < EEXP; e++) if (l[e] > l[i1]) i1 = e;
        int i2 = (i1 == 0) ? 1 : 0;
#pragma unroll
        for (int e = 0; e < EEXP; e++) if (e != i1 && l[e] > l[i2]) i2 = e;
        float p2 = expf(l[i2] - l[i1]);
        float s = 1.f + p2;
        int s1 = atomicAdd(&g_cnt[i1], 1);
        g_tok[i1 * CAP + s1] = t;
        g_gate[i1 * CAP + s1] = 1.f / s;
        g_pos[2 * t + 0] = i1 * CAP + s1;
        int s2 = atomicAdd(&g_cnt[i2], 1);
        g_tok[i2 * CAP + s2] = t;
        g_gate[i2 * CAP + s2] = p2 / s;
        g_pos[2 * t + 1] = i2 * CAP + s2;
    }
}

// ---------------- kernel 2: padded prefix offsets ---------------------------
__global__ void offsets_kernel() {
    if (threadIdx.x == 0) {
        int acc = 0;
#pragma unroll
        for (int e = 0; e < EEXP; e++) {
            g_off[e] = acc;
            acc += ((g_cnt[e] + TM - 1) / TM) * TM;
        }
        g_off[EEXP] = acc;
    }
}

__device__ __forceinline__ int tile_to_expert(int row0, int& m0) {
    if (row0 >= g_off[EEXP]) return -1;
    int e = 0;
#pragma unroll
    for (int k = 1; k < EEXP; k++) if (row0 >= g_off[k]) e = k;
    m0 = row0 - g_off[e];
    if (m0 >= g_cnt[e]) return -1;
    return e;
}

// ---------------- kernel 3: round-copy x -> g_X -----------------------------
__global__ void round_x_kernel(const float* __restrict__ x) {
    int i = blockIdx.x * blockDim.x + threadIdx.x;     // float4 index
    float4 v = ((const float4*)x)[i];
    v.x = tf32r(v.x); v.y = tf32r(v.y); v.z = tf32r(v.z); v.w = tf32r(v.w);
    ((float4*)g_X)[i] = v;
}

// ---------------- kernel T: tiled transpose + tf32 round --------------------
// src [E][R][C] -> dst [E][C][R]
__global__ void transpose_kernel(const float* __restrict__ src,
                                 float* __restrict__ dst, int R, int C) {
    __shared__ float t[32][33];
    int e = blockIdx.z;
    const float* s = src + (size_t)e * R * C;
    float* d = dst + (size_t)e * R * C;
    int c0 = blockIdx.x * 32, r0 = blockIdx.y * 32;
    int tx = threadIdx.x, ty = threadIdx.y;
#pragma unroll
    for (int i = ty; i < 32; i += 8)
        t[i][tx] = s[(size_t)(r0 + i) * C + c0 + tx];
    __syncthreads();
#pragma unroll
    for (int i = ty; i < 32; i += 8)
        d[(size_t)(c0 + i) * R + r0 + tx] = tf32r(t[tx][i]);
}

// ---------------- mma.sync tf32 FFN GEMM ------------------------------------
// C tile 128x128, 8 warps (4m x 2n), warp tile 32x64, m16n8k8 tf32.
// GATHER: A rows gathered from g_X via token list; else A = g_H rows direct.
// RELU: epilogue relu + tf32-round (ffn1) ; else plain f32 (ffn2).
template<int KDIM, int NDIM, bool GATHER, bool RELU>
__global__ void __launch_bounds__(256, 2)
ffn_mma(const float* __restrict__ bias) {
    extern __shared__ char dsm[];
    uint32_t raw = smem_u32(dsm);
    uint32_t sb = (raw + 1023u) & ~1023u;
    char* s = dsm + (sb - raw);

    int tid = threadIdx.x;
    int lane = tid & 31, wid = tid >> 5;
    int g = lane >> 2, tig = lane & 3;
    int m_base = (wid & 3) * 32;
    int n_base = (wid >> 2) * 64;

    int row0 = blockIdx.y * TM, m0;
    int e = tile_to_expert(row0, m0);
    if (e < 0) return;
    int n_rows = g_cnt[e];
    int nblk = blockIdx.x * TN;

    const float* Asrc = GATHER ? g_X : g_H;
    const float* Wt   = GATHER ? g_W1T : g_W2T;
    float*       Outp = GATHER ? g_H : g_Y;

    int* stoks = (int*)s;
    if (GATHER && tid < TM) {
        int m = m0 + tid;
        stoks[tid] = g_tok[e * CAP + (m < n_rows ? m : m0)];
    }
    __syncthreads();

    const float* Wb = Wt + ((size_t)e * NDIM + nblk) * KDIM;

    // cp.async stage issue: each thread 2 iters x (1 A + 1 B) 16B copies
    auto issue = [&](int it) {
        int stg = it & 1;
        uint32_t base = sb + 1024 + stg * STAGE_BYTES;
        int k0 = it * KC;
#pragma unroll
        for (int t = 0; t < 2; t++) {
            int i = tid + t * 256;
            int row = i >> 2, k4 = i & 3;
            const float* asrc = GATHER
                ? Asrc + (size_t)stoks[row] * KDIM + k0 + k4 * 4
                : Asrc + (size_t)(row0 + row) * KDIM + k0 + k4 * 4;
            CP16(base + row * (SROW * 4) + k4 * 16, asrc);
            const float* bsrc = Wb + (size_t)row * KDIM + k0 + k4 * 4;
            CP16(base + (TM * SROW * 4) + row * (SROW * 4) + k4 * 16, bsrc);
        }
    };

    float acc[2][8][4];
#pragma unroll
    for (int mt = 0; mt < 2; mt++)
#pragma unroll
        for (int nt = 0; nt < 8; nt++)
#pragma unroll
            for (int q = 0; q < 4; q++) acc[mt][nt][q] = 0.f;

    const int KST = KDIM / KC;
    issue(0);
    CP_COMMIT();
    for (int it = 0; it < KST; ++it) {
        if (it + 1 < KST) { issue(it + 1); CP_COMMIT(); CP_WAIT1(); }
        else              { CP_WAIT0(); }
        __syncthreads();

        const float* As = (const float*)(s + 1024 + (it & 1) * STAGE_BYTES);
        const float* Bs = As + TM * SROW;
#pragma unroll
        for (int ks = 0; ks < 2; ks++) {
            int kc = ks * 8 + tig;
            uint32_t a[2][4];
#pragma unroll
            for (int mt = 0; mt < 2; mt++) {
                int r0 = m_base + mt * 16 + g;
                a[mt][0] = __float_as_uint(As[r0 * SROW + kc]);
                a[mt][1] = __float_as_uint(As[(r0 + 8) * SROW + kc]);
                a[mt][2] = __float_as_uint(As[r0 * SROW + kc + 4]);
                a[mt][3] = __float_as_uint(As[(r0 + 8) * SROW + kc + 4]);
            }
#pragma unroll
            for (int nt = 0; nt < 8; nt++) {
                int n0 = n_base + nt * 8 + g;
                uint32_t b0 = __float_as_uint(Bs[n0 * SROW + ks * 8 + tig]);
                uint32_t b1 = __float_as_uint(Bs[n0 * SROW + ks * 8 + tig + 4]);
                MMA8(acc[0][nt], a[0], b0, b1);
                MMA8(acc[1][nt], a[1], b0, b1);
            }
        }
        __syncthreads();
    }

    // epilogue
    const float* bb = bias + (size_t)e * NDIM + nblk;
    float* Ob = Outp + (size_t)row0 * NDIM + nblk;
#pragma unroll
    for (int mt = 0; mt < 2; mt++) {
        int r_lo = m_base + mt * 16 + g;
#pragma unroll
        for (int nt = 0; nt < 8; nt++) {
            int col = n_base + nt * 8 + 2 * tig;
            float bv0 = bb[col], bv1 = bb[col + 1];
            float v0 = acc[mt][nt][0] + bv0;
            float v1 = acc[mt][nt][1] + bv1;
            float w0 = acc[mt][nt][2] + bv0;
            float w1 = acc[mt][nt][3] + bv1;
            if (RELU) {
                v0 = tf32r(fmaxf(v0, 0.f)); v1 = tf32r(fmaxf(v1, 0.f));
                w0 = tf32r(fmaxf(w0, 0.f)); w1 = tf32r(fmaxf(w1, 0.f));
            }
            float2 lo = {v0, v1}, hi = {w0, w1};
            *(float2*)(Ob + (size_t)r_lo * NDIM + col) = lo;
            *(float2*)(Ob + (size_t)(r_lo + 8) * NDIM + col) = hi;
        }
    }
}

// ---------------- kernel 5: combine -----------------------------------------
__global__ void combine_kernel(float* __restrict__ out) {
    int t = blockIdx.x;
    int c = threadIdx.x * 4;
    int p1 = g_pos[2 * t + 0];
    int p2 = g_pos[2 * t + 1];
    int e1 = p1 / CAP, e2 = p2 / CAP;
    size_t r1 = (size_t)(g_off[e1] + (p1 - e1 * CAP)) * DDIM;
    size_t r2 = (size_t)(g_off[e2] + (p2 - e2 * CAP)) * DDIM;
    float gv1 = g_gate[p1];
    float gv2 = g_gate[p2];
    float4 y1 = *(const float4*)(g_Y + r1 + c);
    float4 y2 = *(const float4*)(g_Y + r2 + c);
    float4 o;
    o.x = gv1 * y1.x + gv2 * y2.x;
    o.y = gv1 * y1.y + gv2 * y2.y;
    o.z = gv1 * y1.z + gv2 * y2.z;
    o.w = gv1 * y1.w + gv2 * y2.w;
    *(float4*)(out + (size_t)t * DDIM + c) = o;
}

// ---------------- launch ----------------------------------------------------
extern "C" void kernel_launch(void* const* d_in, const int* in_sizes, int n_in,
                              void* d_out, int out_size) {
    const float* x  = (const float*)d_in[0];
    const float* Wg = (const float*)d_in[1];
    const float* bg = (const float*)d_in[2];
    const float* W1 = (const float*)d_in[3];
    const float* b1 = (const float*)d_in[4];
    const float* W2 = (const float*)d_in[5];
    const float* b2 = (const float*)d_in[6];
    float* out = (float*)d_out;

    init_kernel<<<1, 32>>>();
    gating_kernel<<<TCNT / 8, 256>>>(x, Wg, bg);
    offsets_kernel<<<1, 32>>>();

    round_x_kernel<<<(TCNT * DDIM / 4) / 256, 256>>>(x);

    {
        float* w1t; cudaGetSymbolAddress((void**)&w1t, g_W1T);
        float* w2t; cudaGetSymbolAddress((void**)&w2t, g_W2T);
        dim3 b(32, 8);
        // W1 [E][1024][2048] -> g_W1T [E][2048][1024] (rounded)
        transpose_kernel<<<dim3(DFF / 32, DDIM / 32, EEXP), b>>>(W1, w1t, DDIM, DFF);
        // W2 [E][2048][1024] -> g_W2T [E][1024][2048] (rounded)
        transpose_kernel<<<dim3(DDIM / 32, DFF / 32, EEXP), b>>>(W2, w2t, DFF, DDIM);
    }

    ffn_mma<DDIM, DFF, true, true><<<dim3(DFF / TN, MAXTILES), 256, SMEM_BYTES>>>(b1);
    ffn_mma<DFF, DDIM, false, false><<<dim3(DDIM / TN, MAXTILES), 256, SMEM_BYTES>>>(b2);

    combine_kernel<<<TCNT, 256>>>(out);
}

// round 5
// speedup vs baseline: 3.3430x; 1.0690x over previous
#include <cuda_runtime.h>
#include <cstdint>

// Problem constants
#define BSZ   4
#define NTOK  4096
#define DDIM  1024
#define EEXP  8
#define TCNT  (BSZ*NTOK)     // 16384 tokens
#define CAP   TCNT
#define DFF   (2*DDIM)       // 2048

#define TM 128
#define TN 128
#define KC 16                // K floats per stage
#define SROW 20              // padded floats per smem row (bank-conflict-free)
#define NSTAGE 4
#define STAGE_BYTES (TM*SROW*4*2)                 // A(10240)+B(10240)=20480
#define SMEM_BYTES  (2048 + NSTAGE*STAGE_BYTES)   // 83968

#define MAXTILES 264
#define MAXROWS  (MAXTILES * TM)                  // 33792

// ---------------- device scratch -------------------------------------------
__device__ int   g_cnt[EEXP];
__device__ int   g_off[EEXP + 1];
__device__ int   g_tok[EEXP * CAP];
__device__ float g_gate[EEXP * CAP];
__device__ int   g_pos[2 * TCNT];
__device__ float g_X[(size_t)TCNT * DDIM];          // tf32-rounded x (64 MB)
__device__ float g_H[(size_t)MAXROWS * DFF];        // tf32-rounded relu(xW1+b1)
__device__ float g_Y[(size_t)MAXROWS * DDIM];       // f32 hW2+b2
__device__ float g_W1T[(size_t)EEXP * DFF * DDIM];  // [E][N=2048][K=1024] rounded
__device__ float g_W2T[(size_t)EEXP * DDIM * DFF];  // [E][N=1024][K=2048] rounded

// ---------------- helpers ---------------------------------------------------
__device__ __forceinline__ uint32_t smem_u32(const void* p) {
    uint32_t a;
    asm("{ .reg .u64 t; cvta.to.shared.u64 t, %1; cvt.u32.u64 %0, t; }" : "=r"(a) : "l"(p));
    return a;
}
__device__ __forceinline__ float tf32r(float f) {
    uint32_t u;
    asm("cvt.rna.tf32.f32 %0, %1;" : "=r"(u) : "f"(f));
    return __uint_as_float(u);
}
#define CP16(dst, src) \
    asm volatile("cp.async.cg.shared.global [%0], [%1], 16;" :: "r"(dst), "l"(src))
#define CP_COMMIT() asm volatile("cp.async.commit_group;" ::: "memory")
#define CP_WAIT2()  asm volatile("cp.async.wait_group 2;" ::: "memory")
#define CP_WAIT0()  asm volatile("cp.async.wait_group 0;" ::: "memory")

#define MMA8(c, a, b0, b1) \
    asm volatile("mma.sync.aligned.m16n8k8.row.col.f32.tf32.tf32.f32 " \
        "{%0,%1,%2,%3}, {%4,%5,%6,%7}, {%8,%9}, {%0,%1,%2,%3};" \
        : "+f"((c)[0]), "+f"((c)[1]), "+f"((c)[2]), "+f"((c)[3]) \
        : "r"((a)[0]), "r"((a)[1]), "r"((a)[2]), "r"((a)[3]), "r"(b0), "r"(b1))

// ---------------- kernel 0: round-copy x -> g_X (+ zero counters) -----------
__global__ void round_x_kernel(const float* __restrict__ x) {
    if (blockIdx.x == 0 && threadIdx.x < EEXP) g_cnt[threadIdx.x] = 0;
    int i = blockIdx.x * blockDim.x + threadIdx.x;     // float4 index
    float4 v = ((const float4*)x)[i];
    v.x = tf32r(v.x); v.y = tf32r(v.y); v.z = tf32r(v.z); v.w = tf32r(v.w);
    ((float4*)g_X)[i] = v;
}

// ---------------- kernel 1: gating (exact fp32) ------------------------------
__global__ void gating_kernel(const float* __restrict__ x,
                              const float* __restrict__ Wg,
                              const float* __restrict__ bg) {
    __shared__ float sWgT[EEXP][DDIM];
    int tid = threadIdx.x;
    for (int i = tid; i < EEXP * DDIM; i += blockDim.x) {
        int k = i >> 3;
        int e = i & 7;
        sWgT[e][k] = Wg[i];
    }
    __syncthreads();

    int warp = tid >> 5;
    int lane = tid & 31;
    int t = blockIdx.x * 8 + warp;

    float acc[EEXP];
#pragma unroll
    for (int e = 0; e < EEXP; e++) acc[e] = 0.f;
    const float* xr = x + (size_t)t * DDIM;
    for (int k = lane; k < DDIM; k += 32) {
        float xv = xr[k];
#pragma unroll
        for (int e = 0; e < EEXP; e++) acc[e] += xv * sWgT[e][k];
    }
#pragma unroll
    for (int e = 0; e < EEXP; e++) {
#pragma unroll
        for (int off = 16; off > 0; off >>= 1)
            acc[e] += __shfl_xor_sync(0xFFFFFFFFu, acc[e], off);
    }
    if (lane == 0) {
        float l[EEXP];
#pragma unroll
        for (int e = 0; e < EEXP; e++) l[e] = acc[e] + bg[e];
        int i1 = 0;
#pragma unroll
        for (int e = 1; e < EEXP; e++) if (l[e] > l[i1]) i1 = e;
        int i2 = (i1 == 0) ? 1 : 0;
#pragma unroll
        for (int e = 0; e < EEXP; e++) if (e != i1 && l[e] > l[i2]) i2 = e;
        float p2 = expf(l[i2] - l[i1]);
        float s = 1.f + p2;
        int s1 = atomicAdd(&g_cnt[i1], 1);
        g_tok[i1 * CAP + s1] = t;
        g_gate[i1 * CAP + s1] = 1.f / s;
        g_pos[2 * t + 0] = i1 * CAP + s1;
        int s2 = atomicAdd(&g_cnt[i2], 1);
        g_tok[i2 * CAP + s2] = t;
        g_gate[i2 * CAP + s2] = p2 / s;
        g_pos[2 * t + 1] = i2 * CAP + s2;
    }
}

// ---------------- kernel 2: padded prefix offsets ---------------------------
__global__ void offsets_kernel() {
    if (threadIdx.x == 0) {
        int acc = 0;
#pragma unroll
        for (int e = 0; e < EEXP; e++) {
            g_off[e] = acc;
            acc += ((g_cnt[e] + TM - 1) / TM) * TM;
        }
        g_off[EEXP] = acc;
    }
}

__device__ __forceinline__ int tile_to_expert(int row0, int& m0) {
    if (row0 >= g_off[EEXP]) return -1;
    int e = 0;
#pragma unroll
    for (int k = 1; k < EEXP; k++) if (row0 >= g_off[k]) e = k;
    m0 = row0 - g_off[e];
    if (m0 >= g_cnt[e]) return -1;
    return e;
}

// ---------------- kernel T: tiled transpose + tf32 round --------------------
// src [E][R][C] -> dst [E][C][R]
__global__ void transpose_kernel(const float* __restrict__ src,
                                 float* __restrict__ dst, int R, int C) {
    __shared__ float t[32][33];
    int e = blockIdx.z;
    const float* s = src + (size_t)e * R * C;
    float* d = dst + (size_t)e * R * C;
    int c0 = blockIdx.x * 32, r0 = blockIdx.y * 32;
    int tx = threadIdx.x, ty = threadIdx.y;
#pragma unroll
    for (int i = ty; i < 32; i += 8)
        t[i][tx] = s[(size_t)(r0 + i) * C + c0 + tx];
    __syncthreads();
#pragma unroll
    for (int i = ty; i < 32; i += 8)
        d[(size_t)(c0 + i) * R + r0 + tx] = tf32r(t[tx][i]);
}

// ---------------- mma.sync tf32 FFN GEMM (4-stage cp.async pipeline) --------
// C tile 128x128, 8 warps (4m x 2n), warp tile 32x64, m16n8k8 tf32.
template<int KDIM, int NDIM, bool GATHER, bool RELU>
__global__ void __launch_bounds__(256, 2)
ffn_mma(const float* __restrict__ bias) {
    extern __shared__ char dsm[];
    uint32_t raw = smem_u32(dsm);
    uint32_t sb = (raw + 1023u) & ~1023u;
    char* s = dsm + (sb - raw);

    int tid = threadIdx.x;
    int lane = tid & 31, wid = tid >> 5;
    int g = lane >> 2, tig = lane & 3;
    int m_base = (wid & 3) * 32;
    int n_base = (wid >> 2) * 64;

    int row0 = blockIdx.y * TM, m0;
    int e = tile_to_expert(row0, m0);
    if (e < 0) return;
    int n_rows = g_cnt[e];
    int nblk = blockIdx.x * TN;

    const float* Asrc = GATHER ? g_X : g_H;
    const float* Wt   = GATHER ? g_W1T : g_W2T;
    float*       Outp = GATHER ? g_H : g_Y;

    int* stoks = (int*)s;
    if (GATHER && tid < TM) {
        int m = m0 + tid;
        stoks[tid] = g_tok[e * CAP + (m < n_rows ? m : m0)];
    }
    __syncthreads();

    const float* Wb = Wt + ((size_t)e * NDIM + nblk) * KDIM;

    // per-thread fixed copy coords: 2 A + 2 B float4s per stage
    int c_row0 = tid >> 2, c_row1 = (tid + 256) >> 2;
    int c_k4a = (tid & 3) * 16, c_k4b = ((tid + 256) & 3) * 16;
    const float* a_src0 = GATHER ? Asrc + (size_t)stoks[c_row0] * KDIM
                                 : Asrc + (size_t)(row0 + c_row0) * KDIM;
    const float* a_src1 = GATHER ? Asrc + (size_t)stoks[c_row1] * KDIM
                                 : Asrc + (size_t)(row0 + c_row1) * KDIM;
    const float* b_src0 = Wb + (size_t)c_row0 * KDIM;
    const float* b_src1 = Wb + (size_t)c_row1 * KDIM;
    uint32_t d_a0 = c_row0 * (SROW * 4) + c_k4a;
    uint32_t d_a1 = c_row1 * (SROW * 4) + c_k4b;
    uint32_t d_b0 = TM * SROW * 4 + d_a0;
    uint32_t d_b1 = TM * SROW * 4 + d_a1;

    auto issue = [&](int it) {
        uint32_t base = sb + 2048 + (it & (NSTAGE - 1)) * STAGE_BYTES;
        int kb = it * KC * 4;             // byte offset of k0
        CP16(base + d_a0, (const char*)a_src0 + kb + c_k4a);
        CP16(base + d_a1, (const char*)a_src1 + kb + c_k4b);
        CP16(base + d_b0, (const char*)b_src0 + kb + c_k4a);
        CP16(base + d_b1, (const char*)b_src1 + kb + c_k4b);
        CP_COMMIT();
    };

    float acc[2][8][4];
#pragma unroll
    for (int mt = 0; mt < 2; mt++)
#pragma unroll
        for (int nt = 0; nt < 8; nt++)
#pragma unroll
            for (int q = 0; q < 4; q++) acc[mt][nt][q] = 0.f;

    const int KST = KDIM / KC;
    issue(0); issue(1); issue(2);
    for (int it = 0; it < KST; ++it) {
        if (it + 3 < KST) CP_WAIT2(); else CP_WAIT0();
        __syncthreads();

        const float* As = (const float*)(s + 2048 + (it & (NSTAGE - 1)) * STAGE_BYTES);
        const float* Bs = As + TM * SROW;
#pragma unroll
        for (int ks = 0; ks < 2; ks++) {
            int kc = ks * 8 + tig;
            uint32_t a[2][4];
#pragma unroll
            for (int mt = 0; mt < 2; mt++) {
                int r0 = m_base + mt * 16 + g;
                a[mt][0] = __float_as_uint(As[r0 * SROW + kc]);
                a[mt][1] = __float_as_uint(As[(r0 + 8) * SROW + kc]);
                a[mt][2] = __float_as_uint(As[r0 * SROW + kc + 4]);
                a[mt][3] = __float_as_uint(As[(r0 + 8) * SROW + kc + 4]);
            }
#pragma unroll
            for (int nt = 0; nt < 8; nt++) {
                int n0 = n_base + nt * 8 + g;
                uint32_t b0 = __float_as_uint(Bs[n0 * SROW + ks * 8 + tig]);
                uint32_t b1 = __float_as_uint(Bs[n0 * SROW + ks * 8 + tig + 4]);
                MMA8(acc[0][nt], a[0], b0, b1);
                MMA8(acc[1][nt], a[1], b0, b1);
            }
        }
        if (it + 3 < KST) issue(it + 3);
    }

    // epilogue
    const float* bb = bias + (size_t)e * NDIM + nblk;
    float* Ob = Outp + (size_t)row0 * NDIM + nblk;
#pragma unroll
    for (int mt = 0; mt < 2; mt++) {
        int r_lo = m_base + mt * 16 + g;
#pragma unroll
        for (int nt = 0; nt < 8; nt++) {
            int col = n_base + nt * 8 + 2 * tig;
            float bv0 = bb[col], bv1 = bb[col + 1];
            float v0 = acc[mt][nt][0] + bv0;
            float v1 = acc[mt][nt][1] + bv1;
            float w0 = acc[mt][nt][2] + bv0;
            float w1 = acc[mt][nt][3] + bv1;
            if (RELU) {
                v0 = tf32r(fmaxf(v0, 0.f)); v1 = tf32r(fmaxf(v1, 0.f));
                w0 = tf32r(fmaxf(w0, 0.f)); w1 = tf32r(fmaxf(w1, 0.f));
            }
            float2 lo = {v0, v1}, hi = {w0, w1};
            *(float2*)(Ob + (size_t)r_lo * NDIM + col) = lo;
            *(float2*)(Ob + (size_t)(r_lo + 8) * NDIM + col) = hi;
        }
    }
}

// ---------------- kernel 5: combine -----------------------------------------
__global__ void combine_kernel(float* __restrict__ out) {
    int t = blockIdx.x;
    int c = threadIdx.x * 4;
    int p1 = g_pos[2 * t + 0];
    int p2 = g_pos[2 * t + 1];
    int e1 = p1 / CAP, e2 = p2 / CAP;
    size_t r1 = (size_t)(g_off[e1] + (p1 - e1 * CAP)) * DDIM;
    size_t r2 = (size_t)(g_off[e2] + (p2 - e2 * CAP)) * DDIM;
    float gv1 = g_gate[p1];
    float gv2 = g_gate[p2];
    float4 y1 = *(const float4*)(g_Y + r1 + c);
    float4 y2 = *(const float4*)(g_Y + r2 + c);
    float4 o;
    o.x = gv1 * y1.x + gv2 * y2.x;
    o.y = gv1 * y1.y + gv2 * y2.y;
    o.z = gv1 * y1.z + gv2 * y2.z;
    o.w = gv1 * y1.w + gv2 * y2.w;
    *(float4*)(out + (size_t)t * DDIM + c) = o;
}

// ---------------- launch ----------------------------------------------------
extern "C" void kernel_launch(void* const* d_in, const int* in_sizes, int n_in,
                              void* d_out, int out_size) {
    const float* x  = (const float*)d_in[0];
    const float* Wg = (const float*)d_in[1];
    const float* bg = (const float*)d_in[2];
    const float* W1 = (const float*)d_in[3];
    const float* b1 = (const float*)d_in[4];
    const float* W2 = (const float*)d_in[5];
    const float* b2 = (const float*)d_in[6];
    float* out = (float*)d_out;

    cudaFuncSetAttribute(ffn_mma<DDIM, DFF, true, true>,
                         cudaFuncAttributeMaxDynamicSharedMemorySize, SMEM_BYTES);
    cudaFuncSetAttribute(ffn_mma<DFF, DDIM, false, false>,
                         cudaFuncAttributeMaxDynamicSharedMemorySize, SMEM_BYTES);

    // launch order chosen so ffn1 is launch index 5 (ncu -s 5 -c 1 captures it)
    round_x_kernel<<<(TCNT * DDIM / 4) / 256, 256>>>(x);      // 0 (also zeroes cnt)
    gating_kernel<<<TCNT / 8, 256>>>(x, Wg, bg);              // 1
    offsets_kernel<<<1, 32>>>();                              // 2
    {
        float* w1t; cudaGetSymbolAddress((void**)&w1t, g_W1T);
        float* w2t; cudaGetSymbolAddress((void**)&w2t, g_W2T);
        dim3 b(32, 8);
        transpose_kernel<<<dim3(DFF / 32, DDIM / 32, EEXP), b>>>(W1, w1t, DDIM, DFF); // 3
        transpose_kernel<<<dim3(DDIM / 32, DFF / 32, EEXP), b>>>(W2, w2t, DFF, DDIM); // 4
    }
    ffn_mma<DDIM, DFF, true, true><<<dim3(DFF / TN, MAXTILES), 256, SMEM_BYTES>>>(b1);   // 5
    ffn_mma<DFF, DDIM, false, false><<<dim3(DDIM / TN, MAXTILES), 256, SMEM_BYTES>>>(b2); // 6
    combine_kernel<<<TCNT, 256>>>(out);                       // 7
}

// round 8
// speedup vs baseline: 3.8823x; 1.1613x over previous
#include <cuda_runtime.h>
#include <cstdint>

// Problem constants
#define BSZ   4
#define NTOK  4096
#define DDIM  1024
#define EEXP  8
#define TCNT  (BSZ*NTOK)     // 16384 tokens
#define CAP   TCNT
#define DFF   (2*DDIM)       // 2048

#define TM 128
#define TN 128
#define KC 16                // K floats per stage
#define SROW 20              // padded floats per smem row (bank-conflict-free)
#define NSTAGE 4
#define STAGE_BYTES (TM*SROW*4*2)                 // A(10240)+B(10240)=20480
#define SMEM_BYTES  (2048 + NSTAGE*STAGE_BYTES)   // 83968

#define MAXTILES 264
#define MAXROWS  (MAXTILES * TM)                  // 33792

// ---------------- device scratch -------------------------------------------
__device__ int   g_cnt[EEXP];
__device__ int   g_tok[EEXP * CAP];
__device__ float g_gate[EEXP * CAP];
__device__ int   g_pos[2 * TCNT];
__device__ float g_X[(size_t)TCNT * DDIM];          // tf32-rounded x (64 MB)
__device__ float g_H[(size_t)MAXROWS * DFF];        // tf32-rounded relu(xW1+b1)
__device__ float g_Y[(size_t)MAXROWS * DDIM];       // f32 hW2+b2
__device__ float g_W1T[(size_t)EEXP * DFF * DDIM];  // [E][N=2048][K=1024] rounded
__device__ float g_W2T[(size_t)EEXP * DDIM * DFF];  // [E][N=1024][K=2048] rounded

// ---------------- helpers ---------------------------------------------------
__device__ __forceinline__ uint32_t smem_u32(const void* p) {
    uint32_t a;
    asm("{ .reg .u64 t; cvta.to.shared.u64 t, %1; cvt.u32.u64 %0, t; }" : "=r"(a) : "l"(p));
    return a;
}
__device__ __forceinline__ float tf32r(float f) {
    uint32_t u;
    asm("cvt.rna.tf32.f32 %0, %1;" : "=r"(u) : "f"(f));
    return __uint_as_float(u);
}
#define CP16(dst, src) \
    asm volatile("cp.async.cg.shared.global [%0], [%1], 16;" :: "r"(dst), "l"(src))
#define CP_COMMIT() asm volatile("cp.async.commit_group;" ::: "memory")
#define CP_WAIT2()  asm volatile("cp.async.wait_group 2;" ::: "memory")
#define CP_WAIT0()  asm volatile("cp.async.wait_group 0;" ::: "memory")

#define MMA8(c, a, b0, b1) \
    asm volatile("mma.sync.aligned.m16n8k8.row.col.f32.tf32.tf32.f32 " \
        "{%0,%1,%2,%3}, {%4,%5,%6,%7}, {%8,%9}, {%0,%1,%2,%3};" \
        : "+f"((c)[0]), "+f"((c)[1]), "+f"((c)[2]), "+f"((c)[3]) \
        : "r"((a)[0]), "r"((a)[1]), "r"((a)[2]), "r"((a)[3]), "r"(b0), "r"(b1))

#define LDSM4(r, addr) \
    asm volatile("ldmatrix.sync.aligned.m8n8.x4.shared.b16 {%0,%1,%2,%3}, [%4];" \
        : "=r"((r)[0]), "=r"((r)[1]), "=r"((r)[2]), "=r"((r)[3]) : "r"(addr))

// ---------------- transpose + tf32 round: src [E][R][C] -> dst [E][C][R] ----
// ZERO_CNT: block (0,0,0) also zeroes g_cnt (stream-ordered before gating).
template<bool ZERO_CNT>
__global__ void transpose_kernel(const float* __restrict__ src,
                                 float* __restrict__ dst, int R, int C) {
    if (ZERO_CNT && blockIdx.x == 0 && blockIdx.y == 0 && blockIdx.z == 0 &&
        threadIdx.y == 0 && threadIdx.x < EEXP)
        g_cnt[threadIdx.x] = 0;
    __shared__ float t[32][33];
    int e = blockIdx.z;
    const float* s = src + (size_t)e * R * C;
    float* d = dst + (size_t)e * R * C;
    int c0 = blockIdx.x * 32, r0 = blockIdx.y * 32;
    int tx = threadIdx.x, ty = threadIdx.y;
#pragma unroll
    for (int i = ty; i < 32; i += 8)
        t[i][tx] = s[(size_t)(r0 + i) * C + c0 + tx];
    __syncthreads();
#pragma unroll
    for (int i = ty; i < 32; i += 8)
        d[(size_t)(c0 + i) * R + r0 + tx] = tf32r(t[tx][i]);
}

// ---------------- gating (exact fp32) + tf32-round x ------------------------
__global__ void gating_kernel(const float* __restrict__ x,
                              const float* __restrict__ Wg,
                              const float* __restrict__ bg) {
    __shared__ float sWgT[EEXP][DDIM];
    int tid = threadIdx.x;
    int t0 = blockIdx.x * 8;

    // tf32-round this block's 8 token rows into g_X
    for (int i = tid; i < 8 * (DDIM / 4); i += 256) {
        float4 v = ((const float4*)x)[(size_t)t0 * (DDIM / 4) + i];
        v.x = tf32r(v.x); v.y = tf32r(v.y); v.z = tf32r(v.z); v.w = tf32r(v.w);
        ((float4*)g_X)[(size_t)t0 * (DDIM / 4) + i] = v;
    }

    for (int i = tid; i < EEXP * DDIM; i += blockDim.x) {
        int k = i >> 3;
        int e = i & 7;
        sWgT[e][k] = Wg[i];
    }
    __syncthreads();

    int warp = tid >> 5;
    int lane = tid & 31;
    int t = t0 + warp;

    float acc[EEXP];
#pragma unroll
    for (int e = 0; e < EEXP; e++) acc[e] = 0.f;
    const float* xr = x + (size_t)t * DDIM;
    for (int k = lane; k < DDIM; k += 32) {
        float xv = xr[k];
#pragma unroll
        for (int e = 0; e < EEXP; e++) acc[e] += xv * sWgT[e][k];
    }
#pragma unroll
    for (int e = 0; e < EEXP; e++) {
#pragma unroll
        for (int off = 16; off > 0; off >>= 1)
            acc[e] += __shfl_xor_sync(0xFFFFFFFFu, acc[e], off);
    }
    if (lane == 0) {
        float l[EEXP];
#pragma unroll
        for (int e = 0; e < EEXP; e++) l[e] = acc[e] + bg[e];
        int i1 = 0;
#pragma unroll
        for (int e = 1; e < EEXP; e++) if (l[e] > l[i1]) i1 = e;
        int i2 = (i1 == 0) ? 1 : 0;
#pragma unroll
        for (int e = 0; e < EEXP; e++) if (e != i1 && l[e] > l[i2]) i2 = e;
        float p2 = expf(l[i2] - l[i1]);
        float s = 1.f + p2;
        int s1 = atomicAdd(&g_cnt[i1], 1);
        g_tok[i1 * CAP + s1] = t;
        g_gate[i1 * CAP + s1] = 1.f / s;
        g_pos[2 * t + 0] = i1 * CAP + s1;
        int s2 = atomicAdd(&g_cnt[i2], 1);
        g_tok[i2 * CAP + s2] = t;
        g_gate[i2 * CAP + s2] = p2 / s;
        g_pos[2 * t + 1] = i2 * CAP + s2;
    }
}

// ---- inline padded-prefix routing (computed from g_cnt; no offsets kernel) --
__device__ __forceinline__ int tile_to_expert(int row0, int& m0) {
    int acc = 0, e = -1, mm = 0;
#pragma unroll
    for (int k = 0; k < EEXP; k++) {
        int c = g_cnt[k];
        int pad = (c + TM - 1) & ~(TM - 1);
        if (e < 0 && row0 < acc + pad) { e = k; mm = row0 - acc; }
        acc += pad;
    }
    if (e < 0 || mm >= g_cnt[e]) return -1;
    m0 = mm;
    return e;
}

// ---------------- mma.sync tf32 FFN GEMM (ldmatrix + 4-stage cp.async) ------
// C tile 128x128, 8 warps (4m x 2n), warp tile 32x64, m16n8k8 tf32.
template<int KDIM, int NDIM, bool GATHER, bool RELU>
__global__ void __launch_bounds__(256, 2)
ffn_mma(const float* __restrict__ bias) {
    extern __shared__ char dsm[];
    uint32_t raw = smem_u32(dsm);
    uint32_t sb = (raw + 1023u) & ~1023u;
    char* s = dsm + (sb - raw);

    int tid = threadIdx.x;
    int lane = tid & 31, wid = tid >> 5;
    int g = lane >> 2, tig = lane & 3;
    int m_base = (wid & 3) * 32;
    int n_base = (wid >> 2) * 64;

    int row0 = blockIdx.y * TM, m0;
    int e = tile_to_expert(row0, m0);
    if (e < 0) return;
    int n_rows = g_cnt[e];
    int nblk = blockIdx.x * TN;

    const float* Asrc = GATHER ? g_X : g_H;
    const float* Wt   = GATHER ? g_W1T : g_W2T;
    float*       Outp = GATHER ? g_H : g_Y;

    int* stoks = (int*)s;
    if (GATHER && tid < TM) {
        int m = m0 + tid;
        stoks[tid] = g_tok[e * CAP + (m < n_rows ? m : m0)];
    }
    __syncthreads();

    const float* Wb = Wt + ((size_t)e * NDIM + nblk) * KDIM;

    // ---- cp.async copy coords: 2 A + 2 B float4s per thread per stage ----
    int c_row0 = tid >> 2, c_row1 = (tid + 256) >> 2;
    int c_k4a = (tid & 3) * 16, c_k4b = ((tid + 256) & 3) * 16;
    const float* a_src0 = GATHER ? Asrc + (size_t)stoks[c_row0] * KDIM
                                 : Asrc + (size_t)(row0 + c_row0) * KDIM;
    const float* a_src1 = GATHER ? Asrc + (size_t)stoks[c_row1] * KDIM
                                 : Asrc + (size_t)(row0 + c_row1) * KDIM;
    const float* b_src0 = Wb + (size_t)c_row0 * KDIM;
    const float* b_src1 = Wb + (size_t)c_row1 * KDIM;
    uint32_t d_a0 = c_row0 * (SROW * 4) + c_k4a;
    uint32_t d_a1 = c_row1 * (SROW * 4) + c_k4b;
    uint32_t d_b0 = TM * SROW * 4 + d_a0;
    uint32_t d_b1 = TM * SROW * 4 + d_a1;

    auto issue = [&](int it) {
        uint32_t base = sb + 2048 + (it & (NSTAGE - 1)) * STAGE_BYTES;
        int kb = it * KC * 4;
        CP16(base + d_a0, (const char*)a_src0 + kb + c_k4a);
        CP16(base + d_a1, (const char*)a_src1 + kb + c_k4b);
        CP16(base + d_b0, (const char*)b_src0 + kb + c_k4a);
        CP16(base + d_b1, (const char*)b_src1 + kb + c_k4b);
        CP_COMMIT();
    };

    // ---- ldmatrix per-thread byte offsets (within a stage buffer) ----
    int sel = lane >> 3;          // 0..3: x4 matrix selector
    int r8  = lane & 7;
    uint32_t aoff[2];
#pragma unroll
    for (int mt = 0; mt < 2; mt++)
        aoff[mt] = ((m_base + mt * 16 + (sel & 1) * 8 + r8) * SROW + (sel >> 1) * 4) * 4;
    uint32_t boff0 = TM * SROW * 4 +
        ((n_base + ((lane >> 4) & 1) * 8 + r8) * SROW + ((lane >> 3) & 1) * 4) * 4;

    float acc[2][8][4];
#pragma unroll
    for (int mt = 0; mt < 2; mt++)
#pragma unroll
        for (int nt = 0; nt < 8; nt++)
#pragma unroll
            for (int q = 0; q < 4; q++) acc[mt][nt][q] = 0.f;

    const int KST = KDIM / KC;
    issue(0); issue(1); issue(2);
    for (int it = 0; it < KST; ++it) {
        if (it + 3 < KST) CP_WAIT2(); else CP_WAIT0();
        __syncthreads();

        uint32_t sbase = sb + 2048 + (it & (NSTAGE - 1)) * STAGE_BYTES;
#pragma unroll
        for (int ks = 0; ks < 2; ks++) {
            uint32_t kadd = ks * 32;      // 8 floats
            uint32_t a[2][4];
            LDSM4(a[0], sbase + aoff[0] + kadd);
            LDSM4(a[1], sbase + aoff[1] + kadd);
#pragma unroll
            for (int p = 0; p < 4; p++) {
                uint32_t b[4];
                LDSM4(b, sbase + boff0 + p * (16 * SROW * 4) + kadd);
                MMA8(acc[0][2 * p],     a[0], b[0], b[1]);
                MMA8(acc[1][2 * p],     a[1], b[0], b[1]);
                MMA8(acc[0][2 * p + 1], a[0], b[2], b[3]);
                MMA8(acc[1][2 * p + 1], a[1], b[2], b[3]);
            }
        }
        if (it + 3 < KST) issue(it + 3);
    }

    // epilogue
    const float* bb = bias + (size_t)e * NDIM + nblk;
    float* Ob = Outp + (size_t)row0 * NDIM + nblk;
#pragma unroll
    for (int mt = 0; mt < 2; mt++) {
        int r_lo = m_base + mt * 16 + g;
#pragma unroll
        for (int nt = 0; nt < 8; nt++) {
            int col = n_base + nt * 8 + 2 * tig;
            float bv0 = bb[col], bv1 = bb[col + 1];
            float v0 = acc[mt][nt][0] + bv0;
            float v1 = acc[mt][nt][1] + bv1;
            float w0 = acc[mt][nt][2] + bv0;
            float w1 = acc[mt][nt][3] + bv1;
            if (RELU) {
                v0 = tf32r(fmaxf(v0, 0.f)); v1 = tf32r(fmaxf(v1, 0.f));
                w0 = tf32r(fmaxf(w0, 0.f)); w1 = tf32r(fmaxf(w1, 0.f));
            }
            float2 lo = {v0, v1}, hi = {w0, w1};
            *(float2*)(Ob + (size_t)r_lo * NDIM + col) = lo;
            *(float2*)(Ob + (size_t)(r_lo + 8) * NDIM + col) = hi;
        }
    }
}

// ---------------- combine ----------------------------------------------------
__global__ void combine_kernel(float* __restrict__ out) {
    int t = blockIdx.x;
    int c = threadIdx.x * 4;
    int p1 = g_pos[2 * t + 0];
    int p2 = g_pos[2 * t + 1];
    int e1 = p1 / CAP, e2 = p2 / CAP;
    // padded prefix offsets from g_cnt
    int off1 = 0, off2 = 0, acc = 0;
#pragma unroll
    for (int k = 0; k < EEXP; k++) {
        if (k == e1) off1 = acc;
        if (k == e2) off2 = acc;
        acc += (g_cnt[k] + TM - 1) & ~(TM - 1);
    }
    size_t r1 = (size_t)(off1 + (p1 - e1 * CAP)) * DDIM;
    size_t r2 = (size_t)(off2 + (p2 - e2 * CAP)) * DDIM;
    float gv1 = g_gate[p1];
    float gv2 = g_gate[p2];
    float4 y1 = *(const float4*)(g_Y + r1 + c);
    float4 y2 = *(const float4*)(g_Y + r2 + c);
    float4 o;
    o.x = gv1 * y1.x + gv2 * y2.x;
    o.y = gv1 * y1.y + gv2 * y2.y;
    o.z = gv1 * y1.z + gv2 * y2.z;
    o.w = gv1 * y1.w + gv2 * y2.w;
    *(float4*)(out + (size_t)t * DDIM + c) = o;
}

// ---------------- launch ----------------------------------------------------
extern "C" void kernel_launch(void* const* d_in, const int* in_sizes, int n_in,
                              void* d_out, int out_size) {
    const float* x  = (const float*)d_in[0];
    const float* Wg = (const float*)d_in[1];
    const float* bg = (const float*)d_in[2];
    const float* W1 = (const float*)d_in[3];
    const float* b1 = (const float*)d_in[4];
    const float* W2 = (const float*)d_in[5];
    const float* b2 = (const float*)d_in[6];
    float* out = (float*)d_out;

    cudaFuncSetAttribute(ffn_mma<DDIM, DFF, true, true>,
                         cudaFuncAttributeMaxDynamicSharedMemorySize, SMEM_BYTES);
    cudaFuncSetAttribute(ffn_mma<DFF, DDIM, false, false>,
                         cudaFuncAttributeMaxDynamicSharedMemorySize, SMEM_BYTES);

    float* w1t; cudaGetSymbolAddress((void**)&w1t, g_W1T);
    float* w2t; cudaGetSymbolAddress((void**)&w2t, g_W2T);
    dim3 tb(32, 8);

    // order: tW1 (zeroes g_cnt) -> gating -> tW2 -> ffn1(@capture idx 3) -> ffn2 -> combine
    transpose_kernel<true><<<dim3(DFF / 32, DDIM / 32, EEXP), tb>>>(W1, w1t, DDIM, DFF);  // 0
    gating_kernel<<<TCNT / 8, 256>>>(x, Wg, bg);                                          // 1
    transpose_kernel<false><<<dim3(DDIM / 32, DFF / 32, EEXP), tb>>>(W2, w2t, DFF, DDIM); // 2
    ffn_mma<DDIM, DFF, true, true><<<dim3(DFF / TN, MAXTILES), 256, SMEM_BYTES>>>(b1);    // 3
    ffn_mma<DFF, DDIM, false, false><<<dim3(DDIM / TN, MAXTILES), 256, SMEM_BYTES>>>(b2); // 4
    combine_kernel<<<TCNT, 256>>>(out);                                                   // 5
}